// round 6
// baseline (speedup 1.0000x reference)
#include <cuda_runtime.h>
#include <cuda_bf16.h>
#include <cstdint>

// Problem constants (fixed by the dataset): N=1,000,000 points, C=64 channels, K=64 grid
#define KGRID   64
#define NCELLS  (KGRID * KGRID * KGRID)   // 262144
#define NMAX    1000064
#define SCAN_B  512                       // 512 blocks x 512 threads covers 262144

// Scratch in __device__ globals (no allocation allowed)
__device__ int g_counts[NCELLS];
__device__ int g_offsets[NCELLS];   // partial exclusive scan (per 512-block)
__device__ int g_cursor[NCELLS];    // final offsets; bumped to cell end by reorder
__device__ int g_blocksums[SCAN_B];
__device__ int g_pidx[NMAX];
__device__ int g_perm[NMAX];

// ---------------------------------------------------------------------------
// Kernel 1: compute flat voxel index per point + per-cell counts
// ---------------------------------------------------------------------------
__global__ void idx_kernel(const float* __restrict__ points, int n) {
    int i = blockIdx.x * blockDim.x + threadIdx.x;
    if (i >= n) return;
    float x = points[3 * i + 0];
    float y = points[3 * i + 1];
    float z = points[3 * i + 2];
    int ix = (int)floorf((x + 1.0f) * (KGRID * 0.5f));
    int iy = (int)floorf((y + 1.0f) * (KGRID * 0.5f));
    int iz = (int)floorf((z + 1.0f) * (KGRID * 0.5f));
    ix = min(max(ix, 0), KGRID - 1);
    iy = min(max(iy, 0), KGRID - 1);
    iz = min(max(iz, 0), KGRID - 1);
    int idx = ix * (KGRID * KGRID) + iy * KGRID + iz;
    g_pidx[i] = idx;
    atomicAdd(&g_counts[idx], 1);
}

// ---------------------------------------------------------------------------
// Scan stage A: per-block (512-elem) exclusive scan of counts -> g_offsets,
// block totals -> g_blocksums.
// ---------------------------------------------------------------------------
__global__ void scan_block_kernel() {
    __shared__ int s[512];
    int t = threadIdx.x;
    int i = blockIdx.x * 512 + t;
    int v = g_counts[i];
    s[t] = v;
    __syncthreads();
    #pragma unroll
    for (int d = 1; d < 512; d <<= 1) {
        int add = (t >= d) ? s[t - d] : 0;
        __syncthreads();
        s[t] += add;
        __syncthreads();
    }
    int incl = s[t];
    g_offsets[i] = incl - v;                       // exclusive partial
    if (t == 511) g_blocksums[blockIdx.x] = incl;  // block total
}

// ---------------------------------------------------------------------------
// Scan stage B: exclusive scan of the 512 block totals (one block).
// ---------------------------------------------------------------------------
__global__ void scan_top_kernel() {
    __shared__ int s[SCAN_B];
    int t = threadIdx.x;
    int v = g_blocksums[t];
    s[t] = v;
    __syncthreads();
    #pragma unroll
    for (int d = 1; d < SCAN_B; d <<= 1) {
        int add = (t >= d) ? s[t - d] : 0;
        __syncthreads();
        s[t] += add;
        __syncthreads();
    }
    g_blocksums[t] = s[t] - v;   // exclusive
}

// ---------------------------------------------------------------------------
// Scan stage C: finalize offsets into the reorder cursor (single write).
// ---------------------------------------------------------------------------
__global__ void add_offsets_kernel() {
    int i = blockIdx.x * blockDim.x + threadIdx.x;
    if (i >= NCELLS) return;
    g_cursor[i] = g_offsets[i] + g_blocksums[i >> 9];
}

// ---------------------------------------------------------------------------
// Reorder: build permutation grouping point ids by cell.
// After this, g_cursor[cell] == end offset of the cell's segment.
// ---------------------------------------------------------------------------
__global__ void reorder_kernel(int n) {
    int i = blockIdx.x * blockDim.x + threadIdx.x;
    if (i >= n) return;
    int cell = g_pidx[i];
    int pos = atomicAdd(&g_cursor[cell], 1);
    g_perm[pos] = i;
}

// ---------------------------------------------------------------------------
// Gather + mean: ONE WARP PER CELL.
// Up to 32 perm entries loaded in parallel (one per lane), distributed via
// shfl. The two half-warps each handle one point per iteration (lane&15 = the
// float4 channel chunk); halves are combined with shfl_xor(16) at the end.
// Count is uniform per warp -> zero intra-warp divergence.
// ---------------------------------------------------------------------------
__global__ void gather_kernel(const float4* __restrict__ feat4,
                              float4* __restrict__ out) {
    int warp = (blockIdx.x * blockDim.x + threadIdx.x) >> 5;  // == cell
    int lane = threadIdx.x & 31;
    int cell = warp;
    int end  = g_cursor[cell];          // end of segment (post-reorder)
    int cnt  = g_counts[cell];
    int start = end - cnt;
    int q    = lane & 15;
    int half = lane >> 4;

    float4 acc = make_float4(0.f, 0.f, 0.f, 0.f);
    for (int base = 0; base < cnt; base += 32) {
        int m = min(cnt - base, 32);
        int pv = (lane < m) ? g_perm[start + base + lane] : 0;
        int m2 = (m + 1) & ~1;          // round up to even so halves stay converged
        for (int j = half; j < m2; j += 2) {
            int src = (j < m) ? j : 0;
            int p = __shfl_sync(0xffffffffu, pv, src);
            if (j < m) {
                float4 a = __ldg(&feat4[(size_t)p * 16 + q]);
                acc.x += a.x; acc.y += a.y; acc.z += a.z; acc.w += a.w;
            }
        }
    }
    // combine the two half-warp accumulators
    acc.x += __shfl_xor_sync(0xffffffffu, acc.x, 16);
    acc.y += __shfl_xor_sync(0xffffffffu, acc.y, 16);
    acc.z += __shfl_xor_sync(0xffffffffu, acc.z, 16);
    acc.w += __shfl_xor_sync(0xffffffffu, acc.w, 16);

    if (half == 0) {
        float inv = (cnt > 0) ? (1.0f / (float)cnt) : 1.0f;
        acc.x *= inv; acc.y *= inv; acc.z *= inv; acc.w *= inv;
        out[(size_t)cell * 16 + q] = acc;   // empty cells correctly write 0
    }
}

// ---------------------------------------------------------------------------
// Launcher
// inputs: d_in[0] = point_feat (N*64 f32), d_in[1] = points (N*3 f32),
//         d_in[2] = k (int, =64). out: (64,64,64,64) f32
// ---------------------------------------------------------------------------
extern "C" void kernel_launch(void* const* d_in, const int* in_sizes, int n_in,
                              void* d_out, int out_size) {
    const float*  points = (const float*)d_in[1];
    const float4* feat4  = (const float4*)d_in[0];
    float4* out = (float4*)d_out;

    int n = in_sizes[1] / 3;   // number of points

    // zero only the counts scratch (1 MB); everything else is fully rewritten
    void* counts_ptr = nullptr;
    cudaGetSymbolAddress(&counts_ptr, g_counts);
    cudaMemsetAsync(counts_ptr, 0, NCELLS * sizeof(int), 0);

    const int T = 256;
    idx_kernel<<<(n + T - 1) / T, T>>>(points, n);
    scan_block_kernel<<<SCAN_B, 512>>>();
    scan_top_kernel<<<1, SCAN_B>>>();
    add_offsets_kernel<<<NCELLS / T, T>>>();
    reorder_kernel<<<(n + T - 1) / T, T>>>(n);
    // one warp per cell: NCELLS warps, 8 warps per 256-thread block
    gather_kernel<<<NCELLS / 8, T>>>(feat4, out);
}

// round 7
// speedup vs baseline: 1.2613x; 1.2613x over previous
#include <cuda_runtime.h>
#include <cuda_bf16.h>
#include <cstdint>

// Problem constants (fixed by the dataset): N=1,000,000 points, C=64 channels, K=64 grid
#define KGRID   64
#define NCELLS  (KGRID * KGRID * KGRID)   // 262144
#define NMAX    1000064

// Scratch in __device__ globals (no allocation allowed)
__device__ int g_counts[NCELLS];
__device__ int g_cursor[NCELLS];    // per-cell offsets; bumped to segment END by reorder
__device__ int g_total;             // global bump allocator for segment bases
__device__ int g_pidx[NMAX];
__device__ int g_perm[NMAX];

// ---------------------------------------------------------------------------
// Kernel 1: compute flat voxel index per point + per-cell counts
// ---------------------------------------------------------------------------
__global__ void idx_kernel(const float* __restrict__ points, int n) {
    int i = blockIdx.x * blockDim.x + threadIdx.x;
    if (i >= n) return;
    float x = points[3 * i + 0];
    float y = points[3 * i + 1];
    float z = points[3 * i + 2];
    int ix = (int)floorf((x + 1.0f) * (KGRID * 0.5f));
    int iy = (int)floorf((y + 1.0f) * (KGRID * 0.5f));
    int iz = (int)floorf((z + 1.0f) * (KGRID * 0.5f));
    ix = min(max(ix, 0), KGRID - 1);
    iy = min(max(iy, 0), KGRID - 1);
    iz = min(max(iz, 0), KGRID - 1);
    int idx = ix * (KGRID * KGRID) + iy * KGRID + iz;
    g_pidx[i] = idx;
    atomicAdd(&g_counts[idx], 1);
}

// ---------------------------------------------------------------------------
// Kernel 2: fused scan. Each block scans its 512 counts locally, then grabs
// its global base with ONE atomicAdd on g_total. Segment order across blocks
// is atomic-arrival order — irrelevant, since gather only needs each cell's
// segment to be contiguous (start is recovered as cursor_end - count).
// Replaces the previous scan_block + scan_top + add_offsets trio.
// ---------------------------------------------------------------------------
__global__ void scan_fused_kernel() {
    __shared__ int s[512];
    __shared__ int s_base;
    int t = threadIdx.x;
    int i = blockIdx.x * 512 + t;
    int v = g_counts[i];
    s[t] = v;
    __syncthreads();
    #pragma unroll
    for (int d = 1; d < 512; d <<= 1) {
        int add = (t >= d) ? s[t - d] : 0;
        __syncthreads();
        s[t] += add;
        __syncthreads();
    }
    if (t == 511) s_base = atomicAdd(&g_total, s[511]);   // block's segment base
    __syncthreads();
    g_cursor[i] = s_base + s[t] - v;                      // exclusive offset
}

// ---------------------------------------------------------------------------
// Kernel 3: reorder — build permutation grouping point ids by cell.
// After this, g_cursor[cell] == END offset of the cell's segment.
// ---------------------------------------------------------------------------
__global__ void reorder_kernel(int n) {
    int i = blockIdx.x * blockDim.x + threadIdx.x;
    if (i >= n) return;
    int cell = g_pidx[i];
    int pos = atomicAdd(&g_cursor[cell], 1);
    g_perm[pos] = i;
}

// ---------------------------------------------------------------------------
// Kernel 4: gather + mean. 16 threads per cell, thread q owns float4 lane q.
// Points are consumed in predicated batches of 4: clamped perm index +
// 0/1 FMA weight -> no data-dependent branching inside a batch, and
// 4 independent perm loads + 4 independent feat loads in flight per thread.
// ---------------------------------------------------------------------------
__global__ void gather_kernel(const float4* __restrict__ feat4,
                              float4* __restrict__ out) {
    int gid = blockIdx.x * blockDim.x + threadIdx.x;   // NCELLS*16 threads
    int cell = gid >> 4;
    int q    = gid & 15;
    int end   = g_cursor[cell];         // segment end (post-reorder)
    int cnt   = g_counts[cell];
    int start = end - cnt;

    float4 acc = make_float4(0.f, 0.f, 0.f, 0.f);
    for (int b = 0; b < cnt; b += 4) {
        // 4 independent, fully predicated point accumulations
        int   p[4];
        float w[4];
        #pragma unroll
        for (int j = 0; j < 4; j++) {
            int t = b + j;
            int tc = min(t, cnt - 1);   // safe: loop body only runs when cnt >= 1
            p[j] = g_perm[start + tc];
            w[j] = (t < cnt) ? 1.0f : 0.0f;
        }
        #pragma unroll
        for (int j = 0; j < 4; j++) {
            float4 a = __ldg(&feat4[(size_t)p[j] * 16 + q]);
            acc.x = fmaf(a.x, w[j], acc.x);
            acc.y = fmaf(a.y, w[j], acc.y);
            acc.z = fmaf(a.z, w[j], acc.z);
            acc.w = fmaf(a.w, w[j], acc.w);
        }
    }

    float inv = (cnt > 0) ? (1.0f / (float)cnt) : 1.0f;
    acc.x *= inv; acc.y *= inv; acc.z *= inv; acc.w *= inv;
    out[(size_t)cell * 16 + q] = acc;   // empty cells correctly write 0
}

// ---------------------------------------------------------------------------
// Launcher
// inputs: d_in[0] = point_feat (N*64 f32), d_in[1] = points (N*3 f32),
//         d_in[2] = k (int, =64). out: (64,64,64,64) f32
// ---------------------------------------------------------------------------
extern "C" void kernel_launch(void* const* d_in, const int* in_sizes, int n_in,
                              void* d_out, int out_size) {
    const float*  points = (const float*)d_in[1];
    const float4* feat4  = (const float4*)d_in[0];
    float4* out = (float4*)d_out;

    int n = in_sizes[1] / 3;   // number of points

    // zero the counts scratch (1 MB) and the bump allocator
    void* counts_ptr = nullptr;
    void* total_ptr  = nullptr;
    cudaGetSymbolAddress(&counts_ptr, g_counts);
    cudaGetSymbolAddress(&total_ptr,  g_total);
    cudaMemsetAsync(counts_ptr, 0, NCELLS * sizeof(int), 0);
    cudaMemsetAsync(total_ptr,  0, sizeof(int), 0);

    const int T = 256;
    idx_kernel<<<(n + T - 1) / T, T>>>(points, n);
    scan_fused_kernel<<<NCELLS / 512, 512>>>();
    reorder_kernel<<<(n + T - 1) / T, T>>>(n);
    gather_kernel<<<(NCELLS * 16) / T, T>>>(feat4, out);
}

// round 8
// speedup vs baseline: 1.4006x; 1.1104x over previous
#include <cuda_runtime.h>
#include <cuda_bf16.h>
#include <cstdint>

// Problem constants (fixed by the dataset): N=1,000,000 points, C=64 channels, K=64 grid
#define KGRID   64
#define NCELLS  (KGRID * KGRID * KGRID)   // 262144
#define NMAX    1000064

// Scratch in __device__ globals (no allocation allowed)
__device__ int g_counts[NCELLS];
__device__ int g_cursor[NCELLS];    // per-cell offsets; bumped to segment END by reorder
__device__ int g_total;             // global bump allocator for segment bases
__device__ int g_pidx[NMAX];
__device__ int g_perm[NMAX];

__device__ __forceinline__ int cell_of(float x, float y, float z) {
    int ix = (int)floorf((x + 1.0f) * (KGRID * 0.5f));
    int iy = (int)floorf((y + 1.0f) * (KGRID * 0.5f));
    int iz = (int)floorf((z + 1.0f) * (KGRID * 0.5f));
    ix = min(max(ix, 0), KGRID - 1);
    iy = min(max(iy, 0), KGRID - 1);
    iz = min(max(iz, 0), KGRID - 1);
    return ix * (KGRID * KGRID) + iy * KGRID + iz;
}

// ---------------------------------------------------------------------------
// Kernel 1: voxel index per point + per-cell counts.
// 4 points per thread via three float4 loads (12 floats = 4 xyz triples),
// one int4 store for the 4 indices.
// ---------------------------------------------------------------------------
__global__ void idx_kernel(const float4* __restrict__ pts4, int n4, int n) {
    int i4 = blockIdx.x * blockDim.x + threadIdx.x;
    if (i4 >= n4) return;
    int base = i4 * 4;

    if (base + 4 <= n) {
        float4 a = pts4[i4 * 3 + 0];   // x0 y0 z0 x1
        float4 b = pts4[i4 * 3 + 1];   // y1 z1 x2 y2
        float4 c = pts4[i4 * 3 + 2];   // z2 x3 y3 z3
        int c0 = cell_of(a.x, a.y, a.z);
        int c1 = cell_of(a.w, b.x, b.y);
        int c2 = cell_of(b.z, b.w, c.x);
        int c3 = cell_of(c.y, c.z, c.w);
        *(int4*)&g_pidx[base] = make_int4(c0, c1, c2, c3);
        atomicAdd(&g_counts[c0], 1);
        atomicAdd(&g_counts[c1], 1);
        atomicAdd(&g_counts[c2], 1);
        atomicAdd(&g_counts[c3], 1);
    } else {
        const float* p = (const float*)pts4;
        for (int i = base; i < n; i++) {
            int cc = cell_of(p[3 * i], p[3 * i + 1], p[3 * i + 2]);
            g_pidx[i] = cc;
            atomicAdd(&g_counts[cc], 1);
        }
    }
}

// ---------------------------------------------------------------------------
// Kernel 2: fused scan. Each block scans its 512 counts locally, then grabs
// its global base with ONE atomicAdd on g_total. Segment order across blocks
// is atomic-arrival order — irrelevant, since gather only needs each cell's
// segment to be contiguous (start is recovered as cursor_end - count).
// ---------------------------------------------------------------------------
__global__ void scan_fused_kernel() {
    __shared__ int s[512];
    __shared__ int s_base;
    int t = threadIdx.x;
    int i = blockIdx.x * 512 + t;
    int v = g_counts[i];
    s[t] = v;
    __syncthreads();
    #pragma unroll
    for (int d = 1; d < 512; d <<= 1) {
        int add = (t >= d) ? s[t - d] : 0;
        __syncthreads();
        s[t] += add;
        __syncthreads();
    }
    if (t == 511) s_base = atomicAdd(&g_total, s[511]);   // block's segment base
    __syncthreads();
    g_cursor[i] = s_base + s[t] - v;                      // exclusive offset
}

// ---------------------------------------------------------------------------
// Kernel 3: reorder — build permutation grouping point ids by cell.
// After this, g_cursor[cell] == END offset of the cell's segment.
// ---------------------------------------------------------------------------
__global__ void reorder_kernel(int n) {
    int i = blockIdx.x * blockDim.x + threadIdx.x;
    if (i >= n) return;
    int cell = g_pidx[i];
    int pos = atomicAdd(&g_cursor[cell], 1);
    g_perm[pos] = i;
}

// ---------------------------------------------------------------------------
// Kernel 4: gather + mean. 16 threads per cell, thread q owns float4 lane q.
// EXACT loads only (no predicated padding — R7 showed that regresses):
// unroll-4 main loop for MLP, then 2/1 tails.
// ---------------------------------------------------------------------------
__global__ void gather_kernel(const float4* __restrict__ feat4,
                              float4* __restrict__ out) {
    int gid = blockIdx.x * blockDim.x + threadIdx.x;   // NCELLS*16 threads
    int cell = gid >> 4;
    int q    = gid & 15;
    int end   = g_cursor[cell];         // segment end (post-reorder)
    int cnt   = g_counts[cell];
    int start = end - cnt;
    const float4* fq = feat4 + q;

    float4 acc = make_float4(0.f, 0.f, 0.f, 0.f);
    int j = 0;
    for (; j + 4 <= cnt; j += 4) {
        int p0 = g_perm[start + j + 0];
        int p1 = g_perm[start + j + 1];
        int p2 = g_perm[start + j + 2];
        int p3 = g_perm[start + j + 3];
        float4 a = __ldg(fq + (size_t)p0 * 16);
        float4 b = __ldg(fq + (size_t)p1 * 16);
        float4 c = __ldg(fq + (size_t)p2 * 16);
        float4 d = __ldg(fq + (size_t)p3 * 16);
        acc.x += a.x + b.x + c.x + d.x;
        acc.y += a.y + b.y + c.y + d.y;
        acc.z += a.z + b.z + c.z + d.z;
        acc.w += a.w + b.w + c.w + d.w;
    }
    if (j + 2 <= cnt) {
        int p0 = g_perm[start + j + 0];
        int p1 = g_perm[start + j + 1];
        float4 a = __ldg(fq + (size_t)p0 * 16);
        float4 b = __ldg(fq + (size_t)p1 * 16);
        acc.x += a.x + b.x; acc.y += a.y + b.y;
        acc.z += a.z + b.z; acc.w += a.w + b.w;
        j += 2;
    }
    if (j < cnt) {
        int p0 = g_perm[start + j];
        float4 a = __ldg(fq + (size_t)p0 * 16);
        acc.x += a.x; acc.y += a.y; acc.z += a.z; acc.w += a.w;
    }

    float inv = (cnt > 0) ? (1.0f / (float)cnt) : 1.0f;
    acc.x *= inv; acc.y *= inv; acc.z *= inv; acc.w *= inv;
    out[(size_t)cell * 16 + q] = acc;   // empty cells correctly write 0
}

// ---------------------------------------------------------------------------
// Launcher
// inputs: d_in[0] = point_feat (N*64 f32), d_in[1] = points (N*3 f32),
//         d_in[2] = k (int, =64). out: (64,64,64,64) f32
// ---------------------------------------------------------------------------
extern "C" void kernel_launch(void* const* d_in, const int* in_sizes, int n_in,
                              void* d_out, int out_size) {
    const float4* pts4  = (const float4*)d_in[1];
    const float4* feat4 = (const float4*)d_in[0];
    float4* out = (float4*)d_out;

    int n  = in_sizes[1] / 3;        // number of points
    int n4 = (n + 3) / 4;            // 4 points per idx thread

    // zero the counts scratch (1 MB) and the bump allocator
    void* counts_ptr = nullptr;
    void* total_ptr  = nullptr;
    cudaGetSymbolAddress(&counts_ptr, g_counts);
    cudaGetSymbolAddress(&total_ptr,  g_total);
    cudaMemsetAsync(counts_ptr, 0, NCELLS * sizeof(int), 0);
    cudaMemsetAsync(total_ptr,  0, sizeof(int), 0);

    const int T = 256;
    idx_kernel<<<(n4 + T - 1) / T, T>>>(pts4, n4, n);
    scan_fused_kernel<<<NCELLS / 512, 512>>>();
    reorder_kernel<<<(n + T - 1) / T, T>>>(n);
    gather_kernel<<<(NCELLS * 16) / T, T>>>(feat4, out);
}

// round 9
// speedup vs baseline: 1.4483x; 1.0341x over previous
#include <cuda_runtime.h>
#include <cuda_bf16.h>
#include <cstdint>

// Problem constants (fixed by the dataset): N=1,000,000 points, C=64 channels, K=64 grid
#define KGRID   64
#define NCELLS  (KGRID * KGRID * KGRID)   // 262144
#define NMAX    1000064

// Scratch in __device__ globals (no allocation allowed)
__device__ int g_counts[NCELLS];
__device__ int g_cursor[NCELLS];    // per-cell offsets; bumped to segment END by reorder
__device__ int g_total;             // global bump allocator for segment bases
__device__ int g_pidx[NMAX];
__device__ int g_perm[NMAX];

__device__ __forceinline__ int cell_of(float x, float y, float z) {
    int ix = (int)floorf((x + 1.0f) * (KGRID * 0.5f));
    int iy = (int)floorf((y + 1.0f) * (KGRID * 0.5f));
    int iz = (int)floorf((z + 1.0f) * (KGRID * 0.5f));
    ix = min(max(ix, 0), KGRID - 1);
    iy = min(max(iy, 0), KGRID - 1);
    iz = min(max(iz, 0), KGRID - 1);
    return ix * (KGRID * KGRID) + iy * KGRID + iz;
}

// ---------------------------------------------------------------------------
// Kernel 1: voxel index per point + per-cell counts.
// 4 points per thread via three float4 loads (12 floats = 4 xyz triples),
// one int4 store for the 4 indices.
// ---------------------------------------------------------------------------
__global__ void idx_kernel(const float4* __restrict__ pts4, int n4, int n) {
    int i4 = blockIdx.x * blockDim.x + threadIdx.x;
    if (i4 >= n4) return;
    int base = i4 * 4;

    if (base + 4 <= n) {
        float4 a = pts4[i4 * 3 + 0];   // x0 y0 z0 x1
        float4 b = pts4[i4 * 3 + 1];   // y1 z1 x2 y2
        float4 c = pts4[i4 * 3 + 2];   // z2 x3 y3 z3
        int c0 = cell_of(a.x, a.y, a.z);
        int c1 = cell_of(a.w, b.x, b.y);
        int c2 = cell_of(b.z, b.w, c.x);
        int c3 = cell_of(c.y, c.z, c.w);
        *(int4*)&g_pidx[base] = make_int4(c0, c1, c2, c3);
        atomicAdd(&g_counts[c0], 1);
        atomicAdd(&g_counts[c1], 1);
        atomicAdd(&g_counts[c2], 1);
        atomicAdd(&g_counts[c3], 1);
    } else {
        const float* p = (const float*)pts4;
        for (int i = base; i < n; i++) {
            int cc = cell_of(p[3 * i], p[3 * i + 1], p[3 * i + 2]);
            g_pidx[i] = cc;
            atomicAdd(&g_counts[cc], 1);
        }
    }
}

// ---------------------------------------------------------------------------
// Kernel 2: fused scan. Each block scans its 512 counts locally, then grabs
// its global base with ONE atomicAdd on g_total. Segment order across blocks
// is atomic-arrival order — irrelevant, since gather only needs each cell's
// segment to be contiguous (start is recovered as cursor_end - count).
// ---------------------------------------------------------------------------
__global__ void scan_fused_kernel() {
    __shared__ int s[512];
    __shared__ int s_base;
    int t = threadIdx.x;
    int i = blockIdx.x * 512 + t;
    int v = g_counts[i];
    s[t] = v;
    __syncthreads();
    #pragma unroll
    for (int d = 1; d < 512; d <<= 1) {
        int add = (t >= d) ? s[t - d] : 0;
        __syncthreads();
        s[t] += add;
        __syncthreads();
    }
    if (t == 511) s_base = atomicAdd(&g_total, s[511]);   // block's segment base
    __syncthreads();
    g_cursor[i] = s_base + s[t] - v;                      // exclusive offset
}

// ---------------------------------------------------------------------------
// Kernel 3: reorder — build permutation grouping point ids by cell.
// 4 points per thread, one int4 pidx load. After this,
// g_cursor[cell] == END offset of the cell's segment.
// ---------------------------------------------------------------------------
__global__ void reorder_kernel(int n4, int n) {
    int i4 = blockIdx.x * blockDim.x + threadIdx.x;
    if (i4 >= n4) return;
    int base = i4 * 4;

    if (base + 4 <= n) {
        int4 c = *(const int4*)&g_pidx[base];
        int p0 = atomicAdd(&g_cursor[c.x], 1);
        int p1 = atomicAdd(&g_cursor[c.y], 1);
        int p2 = atomicAdd(&g_cursor[c.z], 1);
        int p3 = atomicAdd(&g_cursor[c.w], 1);
        g_perm[p0] = base + 0;
        g_perm[p1] = base + 1;
        g_perm[p2] = base + 2;
        g_perm[p3] = base + 3;
    } else {
        for (int i = base; i < n; i++) {
            int cell = g_pidx[i];
            int pos = atomicAdd(&g_cursor[cell], 1);
            g_perm[pos] = i;
        }
    }
}

// ---------------------------------------------------------------------------
// Kernel 4: gather + mean. 16 threads per cell, thread q owns float4 lane q.
// EXACT loads only (R7: predicated padding regresses). Unroll-4 main + 2/1
// tails. Feature loads use .cs (evict-first) — zero-reuse stream, keep L2
// for metadata (perm/cursor/counts) and the output region.
// ---------------------------------------------------------------------------
__global__ void gather_kernel(const float4* __restrict__ feat4,
                              float4* __restrict__ out) {
    int gid = blockIdx.x * blockDim.x + threadIdx.x;   // NCELLS*16 threads
    int cell = gid >> 4;
    int q    = gid & 15;
    int end   = g_cursor[cell];         // segment end (post-reorder)
    int cnt   = g_counts[cell];
    int start = end - cnt;
    const float4* fq = feat4 + q;

    float4 acc = make_float4(0.f, 0.f, 0.f, 0.f);
    int j = 0;
    for (; j + 4 <= cnt; j += 4) {
        int p0 = g_perm[start + j + 0];
        int p1 = g_perm[start + j + 1];
        int p2 = g_perm[start + j + 2];
        int p3 = g_perm[start + j + 3];
        float4 a = __ldcs(fq + (size_t)p0 * 16);
        float4 b = __ldcs(fq + (size_t)p1 * 16);
        float4 c = __ldcs(fq + (size_t)p2 * 16);
        float4 d = __ldcs(fq + (size_t)p3 * 16);
        acc.x += a.x + b.x + c.x + d.x;
        acc.y += a.y + b.y + c.y + d.y;
        acc.z += a.z + b.z + c.z + d.z;
        acc.w += a.w + b.w + c.w + d.w;
    }
    if (j + 2 <= cnt) {
        int p0 = g_perm[start + j + 0];
        int p1 = g_perm[start + j + 1];
        float4 a = __ldcs(fq + (size_t)p0 * 16);
        float4 b = __ldcs(fq + (size_t)p1 * 16);
        acc.x += a.x + b.x; acc.y += a.y + b.y;
        acc.z += a.z + b.z; acc.w += a.w + b.w;
        j += 2;
    }
    if (j < cnt) {
        int p0 = g_perm[start + j];
        float4 a = __ldcs(fq + (size_t)p0 * 16);
        acc.x += a.x; acc.y += a.y; acc.z += a.z; acc.w += a.w;
    }

    float inv = (cnt > 0) ? (1.0f / (float)cnt) : 1.0f;
    acc.x *= inv; acc.y *= inv; acc.z *= inv; acc.w *= inv;
    out[(size_t)cell * 16 + q] = acc;   // empty cells correctly write 0
}

// ---------------------------------------------------------------------------
// Launcher
// inputs: d_in[0] = point_feat (N*64 f32), d_in[1] = points (N*3 f32),
//         d_in[2] = k (int, =64). out: (64,64,64,64) f32
// ---------------------------------------------------------------------------
extern "C" void kernel_launch(void* const* d_in, const int* in_sizes, int n_in,
                              void* d_out, int out_size) {
    const float4* pts4  = (const float4*)d_in[1];
    const float4* feat4 = (const float4*)d_in[0];
    float4* out = (float4*)d_out;

    int n  = in_sizes[1] / 3;        // number of points
    int n4 = (n + 3) / 4;            // 4 points per idx/reorder thread

    // zero the counts scratch (1 MB) and the bump allocator
    void* counts_ptr = nullptr;
    void* total_ptr  = nullptr;
    cudaGetSymbolAddress(&counts_ptr, g_counts);
    cudaGetSymbolAddress(&total_ptr,  g_total);
    cudaMemsetAsync(counts_ptr, 0, NCELLS * sizeof(int), 0);
    cudaMemsetAsync(total_ptr,  0, sizeof(int), 0);

    const int T = 256;
    idx_kernel<<<(n4 + T - 1) / T, T>>>(pts4, n4, n);
    scan_fused_kernel<<<NCELLS / 512, 512>>>();
    reorder_kernel<<<(n4 + T - 1) / T, T>>>(n4, n);
    gather_kernel<<<(NCELLS * 16) / T, T>>>(feat4, out);
}